// round 14
// baseline (speedup 1.0000x reference)
#include <cuda_runtime.h>
#include <cstdint>

#define NROWS 65536
#define DDIM 512
#define NUM_LABELS 512
#define NUM_DEMOG 4
#define NGROUP (NUM_LABELS * NUM_DEMOG)

#define GRID_STREAM 444
#define TS 128
#define CHUNK 148
#define BR 8
#define NB 4
#define CHUNK_PAD 152
#define NBATCH 19
#define ROWB 2048

// ---- persistent device state (BSS zero; self-cleaning each replay) ----
__device__ int    g_cnt[NGROUP];          // zeroed by k5 finalize
__device__ int    g_off[NGROUP + 1];
__device__ int    g_cursor[NGROUP];
__device__ int    g_seg[NROWS];
__device__ int    g_sorted[NROWS];
__device__ int    g_seg_sorted[NROWS];
__device__ float4 g_sums4[NGROUP * (DDIM / 4)];  // only boundary groups dirtied; k5 re-zeroes
__device__ float  g_ssq[NGROUP];
__device__ double g_intra[NUM_DEMOG];
__device__ int    g_present[NUM_DEMOG];
__device__ int    g_hist_done;            // reset by kA's last CTA
__device__ int    g_fin;                  // reset by finalize

// ===== KA: hist + seg stash; LAST CTA also does the scan (no spin: others exit) =====
__global__ void __launch_bounds__(1024) kA_hist_scan(const void* labels, const void* demog) {
    int i = blockIdx.x * 1024 + threadIdx.x;    // 64 x 1024 = 65536
    int t = threadIdx.x;

    __shared__ int s_is64;
    if (t < 32) {
        unsigned m = __ballot_sync(0xffffffffu, ((const int*)labels)[2 * t + 1] != 0);
        if (t == 0) s_is64 = (m == 0) ? 1 : 0;
    }
    __syncthreads();
    int is64 = s_is64;

    int lab = is64 ? (int)((const long long*)labels)[i] : ((const int*)labels)[i];
    int dem = is64 ? (int)((const long long*)demog)[i]  : ((const int*)demog)[i];
    int seg = dem * NUM_LABELS + lab;
    g_seg[i] = seg;
    atomicAdd(&g_cnt[seg], 1);

    // last-CTA ticket: losers exit immediately (no spin anywhere)
    __shared__ int s_last;
    __threadfence();
    __syncthreads();
    if (t == 0)
        s_last = (atomicAdd(&g_hist_done, 1) == gridDim.x - 1) ? 1 : 0;
    __syncthreads();
    if (!s_last) return;
    __threadfence();   // acquire: all g_cnt visible

    // ---- scan 2048 counts (2 per thread) ----
    int lane = t & 31, warp = t >> 5;
    int a = g_cnt[2 * t];
    int b = g_cnt[2 * t + 1];
    int pair = a + b;
    int v = pair;
    #pragma unroll
    for (int d = 1; d < 32; d <<= 1) {
        int u = __shfl_up_sync(0xffffffffu, v, d);
        if (lane >= d) v += u;
    }
    __shared__ int wsum[32];
    if (lane == 31) wsum[warp] = v;
    __syncthreads();
    if (warp == 0) {
        int w = wsum[lane];
        int x = w;
        #pragma unroll
        for (int d = 1; d < 32; d <<= 1) {
            int u = __shfl_up_sync(0xffffffffu, x, d);
            if (lane >= d) x += u;
        }
        wsum[lane] = x - w;
    }
    __syncthreads();
    int incl = v + wsum[warp];
    int excl = incl - pair;
    g_off[2 * t]        = excl;
    g_off[2 * t + 1]    = excl + a;
    g_cursor[2 * t]     = excl;
    g_cursor[2 * t + 1] = excl + a;
    if (t == 1023) { g_off[NGROUP] = incl; g_hist_done = 0; }
}

// ===== K3: scatter =====
__global__ void __launch_bounds__(1024) k3_scatter() {
    int i = blockIdx.x * 1024 + threadIdx.x;
    int seg = g_seg[i];
    int pos = atomicAdd(&g_cursor[seg], 1);
    g_sorted[pos] = i;
    g_seg_sorted[pos] = seg;
}

// ---------------- cp.async helpers ----------------
__device__ __forceinline__ void cp_async16(uint32_t dst, const float* src) {
    asm volatile("cp.async.cg.shared.global [%0], [%1], 16;" :: "r"(dst), "l"(src));
}
__device__ __forceinline__ void cp_commit() { asm volatile("cp.async.commit_group;" ::: "memory"); }
__device__ __forceinline__ void cp_wait0() { asm volatile("cp.async.wait_group 0;" ::: "memory"); }
__device__ __forceinline__ void cp_wait1() { asm volatile("cp.async.wait_group 1;" ::: "memory"); }
__device__ __forceinline__ void cp_wait2() { asm volatile("cp.async.wait_group 2;" ::: "memory"); }

// ===== K4: stream; contained-group accumulation into per-thread SMEM doubles =====
extern "C" __global__ void __launch_bounds__(TS) k_stream(const float* __restrict__ feats) {
    extern __shared__ __align__(16) char sm[];
    float*  ring = (float*)sm;                                  // 64 KB
    int*    sidx = (int*)(sm + NB * BR * ROWB);                 // 152 ints
    int*    sseg = sidx + CHUNK_PAD;                            // 152 ints
    double* sS   = (double*)(sm + NB * BR * ROWB + 1280);       // 4 x 128 doubles = 4 KB

    int bid = blockIdx.x, t = threadIdx.x;
    int lane = t & 31;
    int lo = bid * CHUNK;
    int hi = min(lo + CHUNK, NROWS);

    #pragma unroll
    for (int d = 0; d < NUM_DEMOG; ++d) sS[d * TS + t] = 0.0;

    for (int i = t; i < CHUNK_PAD; i += TS) {
        int gi = lo + i;
        if (i < CHUNK && gi < NROWS) {
            sidx[i] = g_sorted[gi];
            sseg[i] = g_seg_sorted[gi];
        } else {
            sidx[i] = 0;
            sseg[i] = -1;
        }
    }
    __syncthreads();

    uint32_t ring_base = (uint32_t)__cvta_generic_to_shared(ring) + (uint32_t)t * 16u;
    const float* fbase = feats + (t << 2);

    #pragma unroll
    for (int p = 0; p < 3; ++p) {
        #pragma unroll
        for (int r = 0; r < BR; ++r) {
            const float* src = fbase + ((size_t)sidx[p * BR + r] << 9);
            cp_async16(ring_base + (uint32_t)((p & (NB - 1)) * BR + r) * ROWB, src);
        }
        cp_commit();
    }

    float4 acc = make_float4(0.f, 0.f, 0.f, 0.f);
    float  ssq = 0.f;
    int    cur = -1;
    int    cpk = 0;   // 4 x 8-bit contained-group counts (CTA-uniform)

    #define FLUSH_CUR()                                                          \
        do { if (cur >= 0) {                                                     \
            int s_ = g_off[cur], e_ = g_off[cur + 1];                            \
            if (s_ >= lo && e_ <= hi) {                                          \
                double dot_ = (double)acc.x * acc.x + (double)acc.y * acc.y +    \
                              (double)acc.z * acc.z + (double)acc.w * acc.w;     \
                double cn_ = (double)(e_ - s_);                                  \
                int d_ = cur >> 9;                                               \
                sS[d_ * TS + t] += ((double)ssq - dot_ / cn_) / cn_;             \
                cpk += 1 << (d_ * 8);                                            \
            } else {                                                             \
                float* dst_ = (float*)g_sums4 + ((size_t)cur << 9) + (t << 2);   \
                atomicAdd(dst_ + 0, acc.x); atomicAdd(dst_ + 1, acc.y);          \
                atomicAdd(dst_ + 2, acc.z); atomicAdd(dst_ + 3, acc.w);          \
                float ws_ = ssq;                                                 \
                _Pragma("unroll")                                                \
                for (int o_ = 16; o_ > 0; o_ >>= 1)                              \
                    ws_ += __shfl_down_sync(0xffffffffu, ws_, o_);               \
                if (lane == 0) atomicAdd(&g_ssq[cur], ws_);                      \
            }                                                                    \
        } } while (0)

    for (int b = 0; b < NBATCH; ++b) {
        int k = NBATCH - 1 - b;
        if (k >= 2) cp_wait2(); else if (k == 1) cp_wait1(); else cp_wait0();

        const float* bp = ring + (size_t)((b & (NB - 1)) * BR) * DDIM + (t << 2);
        #pragma unroll
        for (int r = 0; r < BR; ++r) {
            int sg = sseg[b * BR + r];
            if (sg != cur) {
                FLUSH_CUR();
                acc = make_float4(0.f, 0.f, 0.f, 0.f);
                ssq = 0.f;
                cur = sg;
            }
            if (sg >= 0) {
                float4 v = *(const float4*)(bp + (size_t)r * DDIM);
                acc.x += v.x; acc.y += v.y; acc.z += v.z; acc.w += v.w;
                ssq += v.x * v.x + v.y * v.y + v.z * v.z + v.w * v.w;
            }
        }
        int nxt = b + 3;
        if (nxt < NBATCH) {
            #pragma unroll
            for (int r = 0; r < BR; ++r) {
                const float* src = fbase + ((size_t)sidx[nxt * BR + r] << 9);
                cp_async16(ring_base + (uint32_t)((nxt & (NB - 1)) * BR + r) * ROWB, src);
            }
            cp_commit();
        }
    }
    FLUSH_CUR();

    // ---- CTA reduce of contained contributions -> 8 global atomics ----
    __syncthreads();
    #pragma unroll
    for (int s = 64; s > 0; s >>= 1) {
        if (t < s) {
            #pragma unroll
            for (int d = 0; d < NUM_DEMOG; ++d)
                sS[d * TS + t] += sS[d * TS + t + s];
        }
        __syncthreads();
    }
    if (t == 0) {
        #pragma unroll
        for (int d = 0; d < NUM_DEMOG; ++d) {
            int cd = (cpk >> (d * 8)) & 0xff;
            if (cd) {
                atomicAdd(&g_intra[d], sS[d * TS]);
                atomicAdd(&g_present[d], cd);
            }
        }
    }
}

// ===== K5: boundary groups only + ticket finalize + state reset =====
__global__ void __launch_bounds__(128) k5_fin(float* __restrict__ out) {
    __shared__ double wred[4];
    int bid = blockIdx.x, t = threadIdx.x;   // 444 x 128
    int lane = t & 31, w = t >> 5;

    for (int g = bid; g < NGROUP; g += GRID_STREAM) {
        int s = g_off[g], e = g_off[g + 1];
        if (e <= s) continue;
        int ca = s / CHUNK, cb = (e - 1) / CHUNK;
        if (ca == cb) continue;              // contained: handled in k_stream
        float4 v = g_sums4[(size_t)g * 128 + t];
        g_sums4[(size_t)g * 128 + t] = make_float4(0.f, 0.f, 0.f, 0.f);
        double nn = (double)v.x * v.x + (double)v.y * v.y +
                    (double)v.z * v.z + (double)v.w * v.w;
        #pragma unroll
        for (int o = 16; o > 0; o >>= 1)
            nn += __shfl_down_sync(0xffffffffu, nn, o);
        if (lane == 0) wred[w] = nn;
        __syncthreads();
        if (t == 0) {
            double normsq = wred[0] + wred[1] + wred[2] + wred[3];
            double cnt = (double)(e - s);
            double gm = ((double)g_ssq[g] - normsq / cnt) / cnt;
            g_ssq[g] = 0.f;
            atomicAdd(&g_intra[g >> 9], gm);
            atomicAdd(&g_present[g >> 9], 1);
        }
        __syncthreads();
    }

    __shared__ int s_last;
    __threadfence();
    __syncthreads();
    if (t == 0)
        s_last = (atomicAdd(&g_fin, 1) == GRID_STREAM - 1) ? 1 : 0;
    __syncthreads();
    if (!s_last) return;
    __threadfence();

    for (int g = t; g < NGROUP; g += 128) g_cnt[g] = 0;   // clean for next replay

    if (t == 0) {
        double intra[NUM_DEMOG];
        double mu = 0.0;
        #pragma unroll
        for (int d = 0; d < NUM_DEMOG; ++d) {
            int np = g_present[d] > 0 ? g_present[d] : 1;
            intra[d] = g_intra[d] / (double)np;
            mu += intra[d];
        }
        mu /= (double)NUM_DEMOG;
        double loss = 0.0;
        #pragma unroll
        for (int d = 0; d < NUM_DEMOG; ++d) loss += fabs(intra[d] - mu);
        loss /= (double)NUM_DEMOG;
        out[0] = (float)loss;

        #pragma unroll
        for (int d = 0; d < NUM_DEMOG; ++d) { g_intra[d] = 0.0; g_present[d] = 0; }
        g_fin = 0;
        __threadfence();
    }
}

extern "C" void kernel_launch(void* const* d_in, const int* in_sizes, int n_in,
                              void* d_out, int out_size) {
    const float* feats  = (const float*)d_in[0];
    const void*  labels = d_in[1];
    const void*  demog  = d_in[2];
    float* out = (float*)d_out;

    const int smem_stream = NB * BR * ROWB + 1280 + NUM_DEMOG * TS * (int)sizeof(double);
    cudaFuncSetAttribute(k_stream, cudaFuncAttributeMaxDynamicSharedMemorySize, smem_stream);

    kA_hist_scan<<<64, 1024>>>(labels, demog);
    k3_scatter<<<64, 1024>>>();
    k_stream<<<GRID_STREAM, TS, smem_stream>>>(feats);
    k5_fin<<<GRID_STREAM, 128>>>(out);
}

// round 15
// speedup vs baseline: 1.1040x; 1.1040x over previous
#include <cuda_runtime.h>
#include <cstdint>

#define NROWS 65536
#define DDIM 512
#define NUM_LABELS 512
#define NUM_DEMOG 4
#define NGROUP (NUM_LABELS * NUM_DEMOG)

#define GRID_STREAM 444
#define TS 128
#define CHUNK 148
#define BR 8
#define NB 4
#define CHUNK_PAD 152
#define NBATCH 19
#define ROWB 2048

#define NBOUND 442               /* boundaries r=(b+1)*CHUNK < NROWS */

// ---- persistent device state (BSS zero; self-cleaning each replay) ----
__device__ int    g_cnt[NGROUP];          // zeroed by k5 finalize
__device__ int    g_off[NGROUP + 1];
__device__ int    g_cursor[NGROUP];
__device__ int    g_seg[NROWS];
__device__ int    g_sorted[NROWS];
__device__ int    g_seg_sorted[NROWS];
__device__ float4 g_sums4[NGROUP * (DDIM / 4)];  // only straddler groups dirtied; k5 re-zeroes
__device__ float  g_ssq[NGROUP];
__device__ double g_intra[NUM_DEMOG];
__device__ int    g_present[NUM_DEMOG];
__device__ int    g_hist_done;            // reset by kA's last CTA
__device__ int    g_fin;                  // reset by finalize

// ===== KA: hist + seg stash; LAST CTA also does the scan (no spin: others exit) =====
__global__ void __launch_bounds__(1024) kA_hist_scan(const void* labels, const void* demog) {
    int i = blockIdx.x * 1024 + threadIdx.x;    // 64 x 1024 = 65536
    int t = threadIdx.x;

    __shared__ int s_is64;
    if (t < 32) {
        unsigned m = __ballot_sync(0xffffffffu, ((const int*)labels)[2 * t + 1] != 0);
        if (t == 0) s_is64 = (m == 0) ? 1 : 0;
    }
    __syncthreads();
    int is64 = s_is64;

    int lab = is64 ? (int)((const long long*)labels)[i] : ((const int*)labels)[i];
    int dem = is64 ? (int)((const long long*)demog)[i]  : ((const int*)demog)[i];
    int seg = dem * NUM_LABELS + lab;
    g_seg[i] = seg;
    atomicAdd(&g_cnt[seg], 1);

    __shared__ int s_last;
    __threadfence();
    __syncthreads();
    if (t == 0)
        s_last = (atomicAdd(&g_hist_done, 1) == gridDim.x - 1) ? 1 : 0;
    __syncthreads();
    if (!s_last) return;
    __threadfence();   // acquire: all g_cnt visible

    int lane = t & 31, warp = t >> 5;
    int a = g_cnt[2 * t];
    int b = g_cnt[2 * t + 1];
    int pair = a + b;
    int v = pair;
    #pragma unroll
    for (int d = 1; d < 32; d <<= 1) {
        int u = __shfl_up_sync(0xffffffffu, v, d);
        if (lane >= d) v += u;
    }
    __shared__ int wsum[32];
    if (lane == 31) wsum[warp] = v;
    __syncthreads();
    if (warp == 0) {
        int w = wsum[lane];
        int x = w;
        #pragma unroll
        for (int d = 1; d < 32; d <<= 1) {
            int u = __shfl_up_sync(0xffffffffu, x, d);
            if (lane >= d) x += u;
        }
        wsum[lane] = x - w;
    }
    __syncthreads();
    int incl = v + wsum[warp];
    int excl = incl - pair;
    g_off[2 * t]        = excl;
    g_off[2 * t + 1]    = excl + a;
    g_cursor[2 * t]     = excl;
    g_cursor[2 * t + 1] = excl + a;
    if (t == 1023) { g_off[NGROUP] = incl; g_hist_done = 0; }
}

// ===== K3: scatter =====
__global__ void __launch_bounds__(1024) k3_scatter() {
    int i = blockIdx.x * 1024 + threadIdx.x;
    int seg = g_seg[i];
    int pos = atomicAdd(&g_cursor[seg], 1);
    g_sorted[pos] = i;
    g_seg_sorted[pos] = seg;
}

// ---------------- cp.async helpers ----------------
__device__ __forceinline__ void cp_async16(uint32_t dst, const float* src) {
    asm volatile("cp.async.cg.shared.global [%0], [%1], 16;" :: "r"(dst), "l"(src));
}
__device__ __forceinline__ void cp_commit() { asm volatile("cp.async.commit_group;" ::: "memory"); }
__device__ __forceinline__ void cp_wait0() { asm volatile("cp.async.wait_group 0;" ::: "memory"); }
__device__ __forceinline__ void cp_wait1() { asm volatile("cp.async.wait_group 1;" ::: "memory"); }
__device__ __forceinline__ void cp_wait2() { asm volatile("cp.async.wait_group 2;" ::: "memory"); }

// ===== K4: stream (unchanged from R14: smem-double contained-group flush) =====
extern "C" __global__ void __launch_bounds__(TS) k_stream(const float* __restrict__ feats) {
    extern __shared__ __align__(16) char sm[];
    float*  ring = (float*)sm;                                  // 64 KB
    int*    sidx = (int*)(sm + NB * BR * ROWB);                 // 152 ints
    int*    sseg = sidx + CHUNK_PAD;                            // 152 ints
    double* sS   = (double*)(sm + NB * BR * ROWB + 1280);       // 4 x 128 doubles

    int bid = blockIdx.x, t = threadIdx.x;
    int lane = t & 31;
    int lo = bid * CHUNK;
    int hi = min(lo + CHUNK, NROWS);

    #pragma unroll
    for (int d = 0; d < NUM_DEMOG; ++d) sS[d * TS + t] = 0.0;

    for (int i = t; i < CHUNK_PAD; i += TS) {
        int gi = lo + i;
        if (i < CHUNK && gi < NROWS) {
            sidx[i] = g_sorted[gi];
            sseg[i] = g_seg_sorted[gi];
        } else {
            sidx[i] = 0;
            sseg[i] = -1;
        }
    }
    __syncthreads();

    uint32_t ring_base = (uint32_t)__cvta_generic_to_shared(ring) + (uint32_t)t * 16u;
    const float* fbase = feats + (t << 2);

    #pragma unroll
    for (int p = 0; p < 3; ++p) {
        #pragma unroll
        for (int r = 0; r < BR; ++r) {
            const float* src = fbase + ((size_t)sidx[p * BR + r] << 9);
            cp_async16(ring_base + (uint32_t)((p & (NB - 1)) * BR + r) * ROWB, src);
        }
        cp_commit();
    }

    float4 acc = make_float4(0.f, 0.f, 0.f, 0.f);
    float  ssq = 0.f;
    int    cur = -1;
    int    cpk = 0;

    #define FLUSH_CUR()                                                          \
        do { if (cur >= 0) {                                                     \
            int s_ = g_off[cur], e_ = g_off[cur + 1];                            \
            if (s_ >= lo && e_ <= hi) {                                          \
                double dot_ = (double)acc.x * acc.x + (double)acc.y * acc.y +    \
                              (double)acc.z * acc.z + (double)acc.w * acc.w;     \
                double cn_ = (double)(e_ - s_);                                  \
                int d_ = cur >> 9;                                               \
                sS[d_ * TS + t] += ((double)ssq - dot_ / cn_) / cn_;             \
                cpk += 1 << (d_ * 8);                                            \
            } else {                                                             \
                float* dst_ = (float*)g_sums4 + ((size_t)cur << 9) + (t << 2);   \
                atomicAdd(dst_ + 0, acc.x); atomicAdd(dst_ + 1, acc.y);          \
                atomicAdd(dst_ + 2, acc.z); atomicAdd(dst_ + 3, acc.w);          \
                float ws_ = ssq;                                                 \
                _Pragma("unroll")                                                \
                for (int o_ = 16; o_ > 0; o_ >>= 1)                              \
                    ws_ += __shfl_down_sync(0xffffffffu, ws_, o_);               \
                if (lane == 0) atomicAdd(&g_ssq[cur], ws_);                      \
            }                                                                    \
        } } while (0)

    for (int b = 0; b < NBATCH; ++b) {
        int k = NBATCH - 1 - b;
        if (k >= 2) cp_wait2(); else if (k == 1) cp_wait1(); else cp_wait0();

        const float* bp = ring + (size_t)((b & (NB - 1)) * BR) * DDIM + (t << 2);
        #pragma unroll
        for (int r = 0; r < BR; ++r) {
            int sg = sseg[b * BR + r];
            if (sg != cur) {
                FLUSH_CUR();
                acc = make_float4(0.f, 0.f, 0.f, 0.f);
                ssq = 0.f;
                cur = sg;
            }
            if (sg >= 0) {
                float4 v = *(const float4*)(bp + (size_t)r * DDIM);
                acc.x += v.x; acc.y += v.y; acc.z += v.z; acc.w += v.w;
                ssq += v.x * v.x + v.y * v.y + v.z * v.z + v.w * v.w;
            }
        }
        int nxt = b + 3;
        if (nxt < NBATCH) {
            #pragma unroll
            for (int r = 0; r < BR; ++r) {
                const float* src = fbase + ((size_t)sidx[nxt * BR + r] << 9);
                cp_async16(ring_base + (uint32_t)((nxt & (NB - 1)) * BR + r) * ROWB, src);
            }
            cp_commit();
        }
    }
    FLUSH_CUR();

    __syncthreads();
    #pragma unroll
    for (int s = 64; s > 0; s >>= 1) {
        if (t < s) {
            #pragma unroll
            for (int d = 0; d < NUM_DEMOG; ++d)
                sS[d * TS + t] += sS[d * TS + t + s];
        }
        __syncthreads();
    }
    if (t == 0) {
        #pragma unroll
        for (int d = 0; d < NUM_DEMOG; ++d) {
            int cd = (cpk >> (d * 8)) & 0xff;
            if (cd) {
                atomicAdd(&g_intra[d], sS[d * TS]);
                atomicAdd(&g_present[d], cd);
            }
        }
    }
}

// ===== K5: DIRECT boundary lookup (1 boundary per CTA) + ticket finalize =====
__global__ void __launch_bounds__(128) k5_fin(float* __restrict__ out) {
    __shared__ double wred[4];
    int bid = blockIdx.x, t = threadIdx.x;   // NBOUND x 128
    int lane = t & 31, w = t >> 5;

    int r = (bid + 1) * CHUNK;               // chunk boundary row index (< NROWS)
    int g = g_seg_sorted[r];
    int s = g_off[g];
    // straddler at this boundary, owned by this CTA (first boundary inside group)
    if (s < r && s >= r - CHUNK) {
        int e = g_off[g + 1];
        float4 v = g_sums4[(size_t)g * 128 + t];
        g_sums4[(size_t)g * 128 + t] = make_float4(0.f, 0.f, 0.f, 0.f);
        double nn = (double)v.x * v.x + (double)v.y * v.y +
                    (double)v.z * v.z + (double)v.w * v.w;
        #pragma unroll
        for (int o = 16; o > 0; o >>= 1)
            nn += __shfl_down_sync(0xffffffffu, nn, o);
        if (lane == 0) wred[w] = nn;
        __syncthreads();
        if (t == 0) {
            double normsq = wred[0] + wred[1] + wred[2] + wred[3];
            double cnt = (double)(e - s);
            double gm = ((double)g_ssq[g] - normsq / cnt) / cnt;
            g_ssq[g] = 0.f;
            atomicAdd(&g_intra[g >> 9], gm);
            atomicAdd(&g_present[g >> 9], 1);
        }
    }

    // ---- ticket finalize ----
    __shared__ int s_last;
    __threadfence();
    __syncthreads();
    if (t == 0)
        s_last = (atomicAdd(&g_fin, 1) == NBOUND - 1) ? 1 : 0;
    __syncthreads();
    if (!s_last) return;
    __threadfence();

    for (int gg = t; gg < NGROUP; gg += 128) g_cnt[gg] = 0;   // clean for next replay

    if (t == 0) {
        double intra[NUM_DEMOG];
        double mu = 0.0;
        #pragma unroll
        for (int d = 0; d < NUM_DEMOG; ++d) {
            int np = g_present[d] > 0 ? g_present[d] : 1;
            intra[d] = g_intra[d] / (double)np;
            mu += intra[d];
        }
        mu /= (double)NUM_DEMOG;
        double loss = 0.0;
        #pragma unroll
        for (int d = 0; d < NUM_DEMOG; ++d) loss += fabs(intra[d] - mu);
        loss /= (double)NUM_DEMOG;
        out[0] = (float)loss;

        #pragma unroll
        for (int d = 0; d < NUM_DEMOG; ++d) { g_intra[d] = 0.0; g_present[d] = 0; }
        g_fin = 0;
        __threadfence();
    }
}

extern "C" void kernel_launch(void* const* d_in, const int* in_sizes, int n_in,
                              void* d_out, int out_size) {
    const float* feats  = (const float*)d_in[0];
    const void*  labels = d_in[1];
    const void*  demog  = d_in[2];
    float* out = (float*)d_out;

    const int smem_stream = NB * BR * ROWB + 1280 + NUM_DEMOG * TS * (int)sizeof(double);
    cudaFuncSetAttribute(k_stream, cudaFuncAttributeMaxDynamicSharedMemorySize, smem_stream);

    kA_hist_scan<<<64, 1024>>>(labels, demog);
    k3_scatter<<<64, 1024>>>();
    k_stream<<<GRID_STREAM, TS, smem_stream>>>(feats);
    k5_fin<<<NBOUND, 128>>>(out);
}

// round 16
// speedup vs baseline: 1.1091x; 1.0046x over previous
#include <cuda_runtime.h>
#include <cstdint>

#define NROWS 65536
#define DDIM 512
#define NUM_LABELS 512
#define NUM_DEMOG 4
#define NGROUP (NUM_LABELS * NUM_DEMOG)

#define GRID_STREAM 443          /* windows of 148 rows cover 65564 >= 65536 */
#define TS 128
#define CHUNK 148
#define BR 8
#define NB 4
#define ROWB 2048
#define MAXR 512                 /* max rows per CTA (chunk + max group size, 2x margin) */
#define NBMAX (MAXR / BR)

// ---- persistent device state (BSS zero; self-cleaning each replay) ----
__device__ int    g_cnt[NGROUP];          // zeroed by stream finalize
__device__ int    g_off[NGROUP + 1];
__device__ int    g_cursor[NGROUP];
__device__ int    g_seg[NROWS];
__device__ int    g_sorted[NROWS];
__device__ int    g_seg_sorted[NROWS];
__device__ double g_intra[NUM_DEMOG];     // reset by finalize
__device__ int    g_present[NUM_DEMOG];   // reset by finalize
__device__ int    g_hist_done;            // reset by kA's last CTA
__device__ int    g_fin;                  // reset by finalize

// ===== KA: hist + seg stash; LAST CTA also does the scan (no spin) =====
__global__ void __launch_bounds__(1024) kA_hist_scan(const void* labels, const void* demog) {
    int i = blockIdx.x * 1024 + threadIdx.x;    // 64 x 1024 = 65536
    int t = threadIdx.x;

    __shared__ int s_is64;
    if (t < 32) {
        unsigned m = __ballot_sync(0xffffffffu, ((const int*)labels)[2 * t + 1] != 0);
        if (t == 0) s_is64 = (m == 0) ? 1 : 0;
    }
    __syncthreads();
    int is64 = s_is64;

    int lab = is64 ? (int)((const long long*)labels)[i] : ((const int*)labels)[i];
    int dem = is64 ? (int)((const long long*)demog)[i]  : ((const int*)demog)[i];
    int seg = dem * NUM_LABELS + lab;
    g_seg[i] = seg;
    atomicAdd(&g_cnt[seg], 1);

    __shared__ int s_last;
    __threadfence();
    __syncthreads();
    if (t == 0)
        s_last = (atomicAdd(&g_hist_done, 1) == gridDim.x - 1) ? 1 : 0;
    __syncthreads();
    if (!s_last) return;
    __threadfence();   // acquire: all g_cnt visible

    int lane = t & 31, warp = t >> 5;
    int a = g_cnt[2 * t];
    int b = g_cnt[2 * t + 1];
    int pair = a + b;
    int v = pair;
    #pragma unroll
    for (int d = 1; d < 32; d <<= 1) {
        int u = __shfl_up_sync(0xffffffffu, v, d);
        if (lane >= d) v += u;
    }
    __shared__ int wsum[32];
    if (lane == 31) wsum[warp] = v;
    __syncthreads();
    if (warp == 0) {
        int w = wsum[lane];
        int x = w;
        #pragma unroll
        for (int d = 1; d < 32; d <<= 1) {
            int u = __shfl_up_sync(0xffffffffu, x, d);
            if (lane >= d) x += u;
        }
        wsum[lane] = x - w;
    }
    __syncthreads();
    int incl = v + wsum[warp];
    int excl = incl - pair;
    g_off[2 * t]        = excl;
    g_off[2 * t + 1]    = excl + a;
    g_cursor[2 * t]     = excl;
    g_cursor[2 * t + 1] = excl + a;
    if (t == 1023) { g_off[NGROUP] = incl; g_hist_done = 0; }
}

// ===== K3: scatter =====
__global__ void __launch_bounds__(1024) k3_scatter() {
    int i = blockIdx.x * 1024 + threadIdx.x;
    int seg = g_seg[i];
    int pos = atomicAdd(&g_cursor[seg], 1);
    g_sorted[pos] = i;
    g_seg_sorted[pos] = seg;
}

// ---------------- cp.async helpers ----------------
__device__ __forceinline__ void cp_async16(uint32_t dst, const float* src) {
    asm volatile("cp.async.cg.shared.global [%0], [%1], 16;" :: "r"(dst), "l"(src));
}
__device__ __forceinline__ void cp_commit() { asm volatile("cp.async.commit_group;" ::: "memory"); }
__device__ __forceinline__ void cp_wait0() { asm volatile("cp.async.wait_group 0;" ::: "memory"); }
__device__ __forceinline__ void cp_wait1() { asm volatile("cp.async.wait_group 1;" ::: "memory"); }
__device__ __forceinline__ void cp_wait2() { asm volatile("cp.async.wait_group 2;" ::: "memory"); }

// first group-start at row >= r in sorted order
__device__ __forceinline__ int group_start_at(int r) {
    if (r >= NROWS) return NROWS;
    int g = g_seg_sorted[r];
    int s = g_off[g];
    return (s == r) ? r : g_off[g + 1];
}

// ===== K4: stream whole groups per CTA; exit-ticket finalize (no k5) =====
extern "C" __global__ void __launch_bounds__(TS) k_stream(const float* __restrict__ feats,
                                                          float* __restrict__ out) {
    extern __shared__ __align__(16) char sm[];
    float*  ring = (float*)sm;                           // 64 KB
    int*    sidx = (int*)(sm + NB * BR * ROWB);          // MAXR ints
    int*    sseg = sidx + MAXR;                          // MAXR ints
    double* sS   = (double*)(sseg + MAXR);               // 4 x 128 doubles

    int bid = blockIdx.x, t = threadIdx.x;
    int begin = group_start_at(bid * CHUNK);
    int end   = group_start_at((bid + 1) * CHUNK);
    int n = end - begin;
    if (n > MAXR) n = MAXR;                              // safety clamp (never hit statistically)
    int nb = (n + BR - 1) / BR;
    int npad = nb * BR;

    #pragma unroll
    for (int d = 0; d < NUM_DEMOG; ++d) sS[d * TS + t] = 0.0;

    for (int i = t; i < npad; i += TS) {
        if (i < n) {
            sidx[i] = g_sorted[begin + i];
            sseg[i] = g_seg_sorted[begin + i];
        } else {
            sidx[i] = 0;
            sseg[i] = -1;
        }
    }
    __syncthreads();

    uint32_t ring_base = (uint32_t)__cvta_generic_to_shared(ring) + (uint32_t)t * 16u;
    const float* fbase = feats + (t << 2);

    int npro = nb < 3 ? nb : 3;
    for (int p = 0; p < npro; ++p) {
        #pragma unroll
        for (int r = 0; r < BR; ++r) {
            const float* src = fbase + ((size_t)sidx[p * BR + r] << 9);
            cp_async16(ring_base + (uint32_t)((p & (NB - 1)) * BR + r) * ROWB, src);
        }
        cp_commit();
    }

    float4 acc = make_float4(0.f, 0.f, 0.f, 0.f);
    float  ssq = 0.f;
    int    cur = -1;
    long long cpk = 0;   // 4 x 16-bit contained-group counts

    // every group is contained: pure local flush, no atomics, no global accumulators
    #define FLUSH_CUR()                                                          \
        do { if (cur >= 0) {                                                     \
            double dot_ = (double)acc.x * acc.x + (double)acc.y * acc.y +        \
                          (double)acc.z * acc.z + (double)acc.w * acc.w;         \
            double cn_ = (double)(g_off[cur + 1] - g_off[cur]);                  \
            int d_ = cur >> 9;                                                   \
            sS[d_ * TS + t] += ((double)ssq - dot_ / cn_) / cn_;                 \
            cpk += 1LL << (d_ * 16);                                             \
        } } while (0)

    for (int b = 0; b < nb; ++b) {
        int k = nb - 1 - b;
        if (k >= 2) cp_wait2(); else if (k == 1) cp_wait1(); else cp_wait0();

        const float* bp = ring + (size_t)((b & (NB - 1)) * BR) * DDIM + (t << 2);
        #pragma unroll
        for (int r = 0; r < BR; ++r) {
            int sg = sseg[b * BR + r];
            if (sg != cur) {
                FLUSH_CUR();
                acc = make_float4(0.f, 0.f, 0.f, 0.f);
                ssq = 0.f;
                cur = sg;
            }
            if (sg >= 0) {
                float4 v = *(const float4*)(bp + (size_t)r * DDIM);
                acc.x += v.x; acc.y += v.y; acc.z += v.z; acc.w += v.w;
                ssq += v.x * v.x + v.y * v.y + v.z * v.z + v.w * v.w;
            }
        }
        int nxt = b + 3;
        if (nxt < nb) {
            #pragma unroll
            for (int r = 0; r < BR; ++r) {
                const float* src = fbase + ((size_t)sidx[nxt * BR + r] << 9);
                cp_async16(ring_base + (uint32_t)((nxt & (NB - 1)) * BR + r) * ROWB, src);
            }
            cp_commit();
        }
    }
    FLUSH_CUR();

    // ---- CTA reduce of per-thread contributions -> 8 global atomics ----
    __syncthreads();
    #pragma unroll
    for (int s = 64; s > 0; s >>= 1) {
        if (t < s) {
            #pragma unroll
            for (int d = 0; d < NUM_DEMOG; ++d)
                sS[d * TS + t] += sS[d * TS + t + s];
        }
        __syncthreads();
    }
    if (t == 0) {
        #pragma unroll
        for (int d = 0; d < NUM_DEMOG; ++d) {
            int cd = (int)((cpk >> (d * 16)) & 0xffff);
            if (cd) {
                atomicAdd(&g_intra[d], sS[d * TS]);
                atomicAdd(&g_present[d], cd);
            }
        }
    }

    // ---- exit-ticket finalize (no spin; losers exit) ----
    __shared__ int s_last;
    __threadfence();
    __syncthreads();
    if (t == 0)
        s_last = (atomicAdd(&g_fin, 1) == GRID_STREAM - 1) ? 1 : 0;
    __syncthreads();
    if (!s_last) return;
    __threadfence();   // acquire: all g_intra/g_present visible

    for (int gg = t; gg < NGROUP; gg += TS) g_cnt[gg] = 0;   // clean for next replay

    if (t == 0) {
        double intra[NUM_DEMOG];
        double mu = 0.0;
        #pragma unroll
        for (int d = 0; d < NUM_DEMOG; ++d) {
            int np = g_present[d] > 0 ? g_present[d] : 1;
            intra[d] = g_intra[d] / (double)np;
            mu += intra[d];
        }
        mu /= (double)NUM_DEMOG;
        double loss = 0.0;
        #pragma unroll
        for (int d = 0; d < NUM_DEMOG; ++d) loss += fabs(intra[d] - mu);
        loss /= (double)NUM_DEMOG;
        out[0] = (float)loss;

        #pragma unroll
        for (int d = 0; d < NUM_DEMOG; ++d) { g_intra[d] = 0.0; g_present[d] = 0; }
        g_fin = 0;
        __threadfence();
    }
}

extern "C" void kernel_launch(void* const* d_in, const int* in_sizes, int n_in,
                              void* d_out, int out_size) {
    const float* feats  = (const float*)d_in[0];
    const void*  labels = d_in[1];
    const void*  demog  = d_in[2];
    float* out = (float*)d_out;

    const int smem_stream = NB * BR * ROWB + 2 * MAXR * (int)sizeof(int)
                          + NUM_DEMOG * TS * (int)sizeof(double);
    cudaFuncSetAttribute(k_stream, cudaFuncAttributeMaxDynamicSharedMemorySize, smem_stream);

    kA_hist_scan<<<64, 1024>>>(labels, demog);
    k3_scatter<<<64, 1024>>>();
    k_stream<<<GRID_STREAM, TS, smem_stream>>>(feats, out);
}